// round 1
// baseline (speedup 1.0000x reference)
#include <cuda_runtime.h>
#include <cuda_bf16.h>
#include <math.h>

#define Bq 2
#define Tq 1024
#define Dq 2048
#define Hq 8
#define DKq 128
#define DVq 256
#define KDq 1024
#define VDq 2048
#define Mrows (Bq*Tq)   // 2048

// ------------------------- scratch (device globals, no allocation) ----------
__device__ float g_qp[Bq*Tq*KDq];
__device__ float g_kp[Bq*Tq*KDq];
__device__ float g_vp[Bq*Tq*VDq];
__device__ float g_qc[Bq*Tq*KDq];
__device__ float g_kc[Bq*Tq*KDq];
__device__ float g_vc[Bq*Tq*VDq];
__device__ float g_gate[Bq*Tq*VDq];
__device__ float g_gd[Bq*Tq*Hq];
__device__ float g_bt[Bq*Tq*Hq];
__device__ float g_orow[Bq*Tq*VDq];
__device__ float g_onorm[Bq*Tq*VDq];

// ------------------------- SGEMM: C[M,N] = A[M,K] * B[N,K]^T ----------------
// All of M,N multiples of 128, K multiple of 16. fp32.
__global__ void __launch_bounds__(256) sgemm_nt(const float* __restrict__ A,
                                                const float* __restrict__ B,
                                                float* __restrict__ C,
                                                int M, int N, int K)
{
    __shared__ float As[16][136];
    __shared__ float Bs[16][136];
    const int bm = blockIdx.y * 128;
    const int bn = blockIdx.x * 128;
    const int tid = threadIdx.x;
    const int tx = tid & 15;      // 0..15 -> col tile tx*8
    const int ty = tid >> 4;      // 0..15 -> row tile ty*8

    float acc[8][8];
#pragma unroll
    for (int i = 0; i < 8; i++)
#pragma unroll
        for (int j = 0; j < 8; j++) acc[i][j] = 0.f;

    for (int k0 = 0; k0 < K; k0 += 16) {
#pragma unroll
        for (int l = 0; l < 2; l++) {
            int idx = tid + l * 256;         // 0..511
            int r   = idx >> 2;              // 0..127
            int kq  = (idx & 3) * 4;         // 0,4,8,12
            float4 av = *(const float4*)(A + (size_t)(bm + r) * K + k0 + kq);
            As[kq + 0][r] = av.x; As[kq + 1][r] = av.y;
            As[kq + 2][r] = av.z; As[kq + 3][r] = av.w;
            float4 bv = *(const float4*)(B + (size_t)(bn + r) * K + k0 + kq);
            Bs[kq + 0][r] = bv.x; Bs[kq + 1][r] = bv.y;
            Bs[kq + 2][r] = bv.z; Bs[kq + 3][r] = bv.w;
        }
        __syncthreads();
#pragma unroll
        for (int kk = 0; kk < 16; kk++) {
            float a[8], b[8];
            *(float4*)(a)     = *(const float4*)&As[kk][ty * 8];
            *(float4*)(a + 4) = *(const float4*)&As[kk][ty * 8 + 4];
            *(float4*)(b)     = *(const float4*)&Bs[kk][tx * 8];
            *(float4*)(b + 4) = *(const float4*)&Bs[kk][tx * 8 + 4];
#pragma unroll
            for (int i = 0; i < 8; i++)
#pragma unroll
                for (int j = 0; j < 8; j++)
                    acc[i][j] += a[i] * b[j];
        }
        __syncthreads();
    }

#pragma unroll
    for (int i = 0; i < 8; i++) {
        float4 c0 = make_float4(acc[i][0], acc[i][1], acc[i][2], acc[i][3]);
        float4 c1 = make_float4(acc[i][4], acc[i][5], acc[i][6], acc[i][7]);
        float* crow = C + (size_t)(bm + ty * 8 + i) * N + bn + tx * 8;
        *(float4*)(crow)     = c0;
        *(float4*)(crow + 4) = c1;
    }
}

// ------------------------- a/b projections -> decay g and beta --------------
__device__ __forceinline__ float softplus_f(float x) {
    return fmaxf(x, 0.f) + log1pf(expf(-fabsf(x)));
}

__global__ void proj_ab_kernel(const float* __restrict__ h,
                               const float* __restrict__ a_w,
                               const float* __restrict__ b_w,
                               const float* __restrict__ A_log,
                               const float* __restrict__ dt_bias,
                               float* __restrict__ gd, float* __restrict__ bt)
{
    int w = (blockIdx.x * blockDim.x + threadIdx.x) >> 5;   // row id 0..2047
    int lane = threadIdx.x & 31;
    if (w >= Mrows) return;
    const float* hr = h + (size_t)w * Dq;
    float acc[16];
#pragma unroll
    for (int p = 0; p < 16; p++) acc[p] = 0.f;
    for (int j = lane * 4; j < Dq; j += 128) {
        float4 hv = *(const float4*)(hr + j);
#pragma unroll
        for (int p = 0; p < 8; p++) {
            float4 av = *(const float4*)(a_w + (size_t)p * Dq + j);
            acc[p] += hv.x * av.x + hv.y * av.y + hv.z * av.z + hv.w * av.w;
            float4 bv = *(const float4*)(b_w + (size_t)p * Dq + j);
            acc[8 + p] += hv.x * bv.x + hv.y * bv.y + hv.z * bv.z + hv.w * bv.w;
        }
    }
#pragma unroll
    for (int p = 0; p < 16; p++)
#pragma unroll
        for (int m = 16; m; m >>= 1)
            acc[p] += __shfl_xor_sync(0xffffffffu, acc[p], m);

    if (lane < 8) {
        float x = acc[lane] + dt_bias[lane];
        gd[w * Hq + lane] = -expf(A_log[lane]) * softplus_f(x);
    } else if (lane < 16) {
        int p = lane - 8;
        bt[w * Hq + p] = 1.f / (1.f + expf(-acc[lane]));
    }
}

// ------------------------- depthwise causal conv (K=4) + SiLU ---------------
__global__ void conv_silu_kernel(const float* __restrict__ in,
                                 const float* __restrict__ w,
                                 float* __restrict__ out, int T, int C)
{
    int i = blockIdx.x * blockDim.x + threadIdx.x;   // over B*T*C
    int c = i % C;
    int t = (i / C) % T;
    float4 wc = *(const float4*)(w + (size_t)c * 4);
    float acc = 0.f;
    const float* base = in + i;
    if (t >= 3) acc += base[-3 * C] * wc.x;
    if (t >= 2) acc += base[-2 * C] * wc.y;
    if (t >= 1) acc += base[-1 * C] * wc.z;
    acc += base[0] * wc.w;
    out[i] = acc / (1.f + expf(-acc));   // SiLU
}

// ------------------------- l2norm over head dim (128), in place -------------
__global__ void l2norm_kernel(float* __restrict__ x)
{
    int w = (blockIdx.x * blockDim.x + threadIdx.x) >> 5;   // (b,t,h) id
    int lane = threadIdx.x & 31;
    float* row = x + (size_t)w * DKq;
    float4 a = *(float4*)(row + lane * 4);
    float ss = a.x * a.x + a.y * a.y + a.z * a.z + a.w * a.w;
#pragma unroll
    for (int m = 16; m; m >>= 1) ss += __shfl_xor_sync(0xffffffffu, ss, m);
    float r = rsqrtf(ss + 1e-6f);
    a.x *= r; a.y *= r; a.z *= r; a.w *= r;
    *(float4*)(row + lane * 4) = a;
}

// ------------------------- gated delta-rule scan ----------------------------
// grid (DV/32, H, B), block 128. Each v-column owned by 4 lanes (32 rows each).
#define TS 16
__global__ void __launch_bounds__(128) scan_kernel(const float* __restrict__ q,
                                                   const float* __restrict__ k,
                                                   const float* __restrict__ v,
                                                   const float* __restrict__ gdec,
                                                   const float* __restrict__ beta,
                                                   float* __restrict__ o)
{
    const int vchunk = blockIdx.x;
    const int h = blockIdx.y;
    const int b = blockIdx.z;
    const int tid = threadIdx.x;
    const int warp = tid >> 5, lane = tid & 31;
    const int col = (warp << 3) + (lane >> 2);   // 0..31 within chunk
    const int rgrp = lane & 3;                   // 32-row group
    const int c0 = vchunk * 32;

    __shared__ float ks[TS * 144];
    __shared__ float qs[TS * 144];
    __shared__ float vs[TS * 32];
    __shared__ float gs[TS];
    __shared__ float bs[TS];

    float S[32];
#pragma unroll
    for (int i = 0; i < 32; i++) S[i] = 0.f;
    const float scale = 0.08838834764831843f;   // 128^-0.5

    for (int t0 = 0; t0 < Tq; t0 += TS) {
        __syncthreads();
#pragma unroll
        for (int j = 0; j < 4; j++) {
            int idx = tid + j * 128;           // 0..511
            int s = idx >> 5, f = idx & 31;    // step, float4-within-step
            size_t gofs = ((size_t)(b * Tq + t0 + s)) * KDq + h * DKq + f * 4;
            float4 kk = *(const float4*)(k + gofs);
            float4 qq = *(const float4*)(q + gofs);
            int sofs = s * 144 + (f >> 3) * 36 + (f & 7) * 4;
            *(float4*)(ks + sofs) = kk;
            *(float4*)(qs + sofs) = qq;
        }
        {
            int s = tid >> 3, f = tid & 7;
            size_t gofs = ((size_t)(b * Tq + t0 + s)) * VDq + h * DVq + c0 + f * 4;
            *(float4*)(vs + s * 32 + f * 4) = *(const float4*)(v + gofs);
        }
        if (tid < TS) gs[tid] = gdec[(size_t)(b * Tq + t0 + tid) * Hq + h];
        else if (tid < 2 * TS) bs[tid - TS] = beta[(size_t)(b * Tq + t0 + tid - TS) * Hq + h];
        __syncthreads();

#pragma unroll 1
        for (int s = 0; s < TS; s++) {
            float eg = expf(gs[s]);
            const float* ksr = ks + s * 144 + rgrp * 36;
            const float* qsr = qs + s * 144 + rgrp * 36;
            float4 kf[8];
            float kv0 = 0.f, kv1 = 0.f, kv2 = 0.f, kv3 = 0.f;
#pragma unroll
            for (int i = 0; i < 8; i++) {
                kf[i] = *(const float4*)(ksr + i * 4);
                kv0 += kf[i].x * S[4 * i + 0];
                kv1 += kf[i].y * S[4 * i + 1];
                kv2 += kf[i].z * S[4 * i + 2];
                kv3 += kf[i].w * S[4 * i + 3];
            }
            float kv = (kv0 + kv1) + (kv2 + kv3);
            kv += __shfl_xor_sync(0xffffffffu, kv, 1);
            kv += __shfl_xor_sync(0xffffffffu, kv, 2);
            float u = (vs[s * 32 + col] - kv * eg) * bs[s];
            float o0 = 0.f, o1 = 0.f, o2 = 0.f, o3 = 0.f;
#pragma unroll
            for (int i = 0; i < 8; i++) {
                float4 qf = *(const float4*)(qsr + i * 4);
                S[4 * i + 0] = S[4 * i + 0] * eg + kf[i].x * u;
                S[4 * i + 1] = S[4 * i + 1] * eg + kf[i].y * u;
                S[4 * i + 2] = S[4 * i + 2] * eg + kf[i].z * u;
                S[4 * i + 3] = S[4 * i + 3] * eg + kf[i].w * u;
                o0 += qf.x * S[4 * i + 0];
                o1 += qf.y * S[4 * i + 1];
                o2 += qf.z * S[4 * i + 2];
                o3 += qf.w * S[4 * i + 3];
            }
            float ot = (o0 + o1) + (o2 + o3);
            ot += __shfl_xor_sync(0xffffffffu, ot, 1);
            ot += __shfl_xor_sync(0xffffffffu, ot, 2);
            if (rgrp == 0)
                o[(size_t)(b * Tq + t0 + s) * VDq + h * DVq + c0 + col] = ot * scale;
        }
    }
}

// ------------------------- gated RMSNorm ------------------------------------
__global__ void rmsnorm_gate_kernel(const float* __restrict__ o,
                                    const float* __restrict__ gate,
                                    const float* __restrict__ nw,
                                    float* __restrict__ out)
{
    int w = (blockIdx.x * blockDim.x + threadIdx.x) >> 5;   // (b,t,h) id
    int lane = threadIdx.x & 31;
    const float* orow = o + (size_t)w * DVq;
    float4 o0 = *(const float4*)(orow + lane * 4);
    float4 o1 = *(const float4*)(orow + 128 + lane * 4);
    float ss = o0.x * o0.x + o0.y * o0.y + o0.z * o0.z + o0.w * o0.w
             + o1.x * o1.x + o1.y * o1.y + o1.z * o1.z + o1.w * o1.w;
#pragma unroll
    for (int m = 16; m; m >>= 1) ss += __shfl_xor_sync(0xffffffffu, ss, m);
    float r = rsqrtf(ss * (1.f / 256.f) + 1e-5f);
    const float* grow = gate + (size_t)w * DVq;
    float4 g0 = *(const float4*)(grow + lane * 4);
    float4 g1 = *(const float4*)(grow + 128 + lane * 4);
    float4 w0 = *(const float4*)(nw + lane * 4);
    float4 w1 = *(const float4*)(nw + 128 + lane * 4);
    float* out_row = out + (size_t)w * DVq;
    float4 r0, r1;
    r0.x = o0.x * r * w0.x * (g0.x / (1.f + expf(-g0.x)));
    r0.y = o0.y * r * w0.y * (g0.y / (1.f + expf(-g0.y)));
    r0.z = o0.z * r * w0.z * (g0.z / (1.f + expf(-g0.z)));
    r0.w = o0.w * r * w0.w * (g0.w / (1.f + expf(-g0.w)));
    r1.x = o1.x * r * w1.x * (g1.x / (1.f + expf(-g1.x)));
    r1.y = o1.y * r * w1.y * (g1.y / (1.f + expf(-g1.y)));
    r1.z = o1.z * r * w1.z * (g1.z / (1.f + expf(-g1.z)));
    r1.w = o1.w * r * w1.w * (g1.w / (1.f + expf(-g1.w)));
    *(float4*)(out_row + lane * 4) = r0;
    *(float4*)(out_row + 128 + lane * 4) = r1;
}

// ------------------------- launch -------------------------------------------
extern "C" void kernel_launch(void* const* d_in, const int* in_sizes, int n_in,
                              void* d_out, int out_size)
{
    const float* h        = (const float*)d_in[0];
    const float* q_w      = (const float*)d_in[1];
    const float* k_w      = (const float*)d_in[2];
    const float* v_w      = (const float*)d_in[3];
    const float* a_w      = (const float*)d_in[4];
    const float* b_w      = (const float*)d_in[5];
    const float* g_w      = (const float*)d_in[6];
    const float* o_w      = (const float*)d_in[7];
    const float* q_conv_w = (const float*)d_in[8];
    const float* k_conv_w = (const float*)d_in[9];
    const float* v_conv_w = (const float*)d_in[10];
    const float* A_log    = (const float*)d_in[11];
    const float* dt_bias  = (const float*)d_in[12];
    const float* o_norm_w = (const float*)d_in[13];
    float* out = (float*)d_out;

    float *qp, *kp, *vp, *qc, *kc, *vc, *gate, *gd, *bt, *orow, *onorm;
    cudaGetSymbolAddress((void**)&qp, g_qp);
    cudaGetSymbolAddress((void**)&kp, g_kp);
    cudaGetSymbolAddress((void**)&vp, g_vp);
    cudaGetSymbolAddress((void**)&qc, g_qc);
    cudaGetSymbolAddress((void**)&kc, g_kc);
    cudaGetSymbolAddress((void**)&vc, g_vc);
    cudaGetSymbolAddress((void**)&gate, g_gate);
    cudaGetSymbolAddress((void**)&gd, g_gd);
    cudaGetSymbolAddress((void**)&bt, g_bt);
    cudaGetSymbolAddress((void**)&orow, g_orow);
    cudaGetSymbolAddress((void**)&onorm, g_onorm);

    // 1) projections (fp32 SGEMM, NT)
    sgemm_nt<<<dim3(KDq / 128, Mrows / 128), 256>>>(h, q_w, qp, Mrows, KDq, Dq);
    sgemm_nt<<<dim3(KDq / 128, Mrows / 128), 256>>>(h, k_w, kp, Mrows, KDq, Dq);
    sgemm_nt<<<dim3(VDq / 128, Mrows / 128), 256>>>(h, v_w, vp, Mrows, VDq, Dq);
    sgemm_nt<<<dim3(VDq / 128, Mrows / 128), 256>>>(h, g_w, gate, Mrows, VDq, Dq);

    // 2) a/b projections -> decay + beta
    proj_ab_kernel<<<(Mrows * 32) / 256, 256>>>(h, a_w, b_w, A_log, dt_bias, gd, bt);

    // 3) causal depthwise conv + SiLU
    conv_silu_kernel<<<(Bq * Tq * KDq) / 256, 256>>>(qp, q_conv_w, qc, Tq, KDq);
    conv_silu_kernel<<<(Bq * Tq * KDq) / 256, 256>>>(kp, k_conv_w, kc, Tq, KDq);
    conv_silu_kernel<<<(Bq * Tq * VDq) / 256, 256>>>(vp, v_conv_w, vc, Tq, VDq);

    // 4) l2 normalize q,k per head
    l2norm_kernel<<<(Bq * Tq * Hq * 32) / 256, 256>>>(qc);
    l2norm_kernel<<<(Bq * Tq * Hq * 32) / 256, 256>>>(kc);

    // 5) gated delta-rule recurrence
    scan_kernel<<<dim3(DVq / 32, Hq, Bq), 128>>>(qc, kc, vc, gd, bt, orow);

    // 6) gated RMSNorm
    rmsnorm_gate_kernel<<<(Bq * Tq * Hq * 32) / 256, 256>>>(orow, gate, o_norm_w, onorm);

    // 7) output projection -> d_out
    sgemm_nt<<<dim3(Dq / 128, Mrows / 128), 256>>>(onorm, o_w, out, Mrows, Dq, Dq);
}

// round 3
// speedup vs baseline: 1.9999x; 1.9999x over previous
#include <cuda_runtime.h>
#include <cuda_bf16.h>
#include <math.h>
#include <stdint.h>

#define Bq 2
#define Tq 1024
#define Dq 2048
#define Hq 8
#define DKq 128
#define DVq 256
#define KDq 1024
#define VDq 2048
#define Mrows (Bq*Tq)   // 2048
#define GK 2048         // K for every big GEMM

// ------------------------- scratch (device globals) -------------------------
__device__ float g_qp[Mrows*KDq];
__device__ float g_kp[Mrows*KDq];
__device__ float g_vp[Mrows*VDq];
__device__ float g_qc[Mrows*KDq];
__device__ float g_kc[Mrows*KDq];
__device__ float g_vc[Mrows*VDq];
__device__ float g_gate[Mrows*VDq];
__device__ float g_gd[Mrows*Hq];
__device__ float g_bt[Mrows*Hq];
__device__ float g_orow[Mrows*VDq];

// bf16 split (hi/lo) operands
__device__ __nv_bfloat16 g_hh[Mrows*Dq],  g_hl[Mrows*Dq];
__device__ __nv_bfloat16 g_qwh[KDq*Dq],   g_qwl[KDq*Dq];
__device__ __nv_bfloat16 g_kwh[KDq*Dq],   g_kwl[KDq*Dq];
__device__ __nv_bfloat16 g_vwh[VDq*Dq],   g_vwl[VDq*Dq];
__device__ __nv_bfloat16 g_gwh[VDq*Dq],   g_gwl[VDq*Dq];
__device__ __nv_bfloat16 g_owh[Dq*VDq],   g_owl[Dq*VDq];
__device__ __nv_bfloat16 g_onh[Mrows*VDq], g_onl[Mrows*VDq];

// ------------------------- helpers ------------------------------------------
__device__ __forceinline__ uint32_t smem_u32(const void* p) {
    uint32_t a;
    asm("{ .reg .u64 t; cvta.to.shared.u64 t, %1; cvt.u32.u64 %0, t; }" : "=r"(a) : "l"(p));
    return a;
}
__device__ __forceinline__ void cp16(uint32_t dst, const void* src) {
    asm volatile("cp.async.cg.shared.global [%0], [%1], 16;" :: "r"(dst), "l"(src));
}
__device__ __forceinline__ void cp_commit() {
    asm volatile("cp.async.commit_group;" ::: "memory");
}
template <int N>
__device__ __forceinline__ void cp_wait() {
    asm volatile("cp.async.wait_group %0;" :: "n"(N) : "memory");
}
__device__ __forceinline__ void ldsm_x4(uint32_t addr, uint32_t* r) {
    asm volatile("ldmatrix.sync.aligned.m8n8.x4.shared.b16 {%0,%1,%2,%3}, [%4];"
                 : "=r"(r[0]), "=r"(r[1]), "=r"(r[2]), "=r"(r[3]) : "r"(addr));
}
__device__ __forceinline__ void mma_bf16(float* c, const uint32_t* a, const uint32_t* b) {
    asm volatile(
        "mma.sync.aligned.m16n8k16.row.col.f32.bf16.bf16.f32 "
        "{%0,%1,%2,%3}, {%4,%5,%6,%7}, {%8,%9}, {%0,%1,%2,%3};"
        : "+f"(c[0]), "+f"(c[1]), "+f"(c[2]), "+f"(c[3])
        : "r"(a[0]), "r"(a[1]), "r"(a[2]), "r"(a[3]), "r"(b[0]), "r"(b[1]));
}

// ------------------------- split bf16 HMMA GEMM -----------------------------
// C[M,N] = A[M,K]*B[N,K]^T, A/B as bf16 hi/lo pairs, K = GK.
// smem tile: 128 rows x 32 bf16, row stride 40 bf16 (80 B) -> conflict-free ldmatrix.
#define ROWB 80                      // bytes per smem row
#define MATB (128*ROWB)              // 10240 B per matrix
#define STGB (4*MATB)                // Ah,Al,Bh,Bl per stage
#define SMEM_GEMM (2*STGB)           // 81920 B

__global__ void __launch_bounds__(256) bgemm_nt_split(
    const __nv_bfloat16* __restrict__ Ah, const __nv_bfloat16* __restrict__ Al,
    const __nv_bfloat16* __restrict__ Bh, const __nv_bfloat16* __restrict__ Bl,
    float* __restrict__ C, int N)
{
    extern __shared__ char smem[];
    const uint32_t sb = smem_u32(smem);
    const int tid = threadIdx.x, wid = tid >> 5, lane = tid & 31;
    const int bm = blockIdx.y * 128, bn = blockIdx.x * 128;
    const int wm = (wid >> 1) * 32;        // warp m offset (4 warps)
    const int wn = (wid & 1) * 64;         // warp n offset (2 warps)

    float acc[2][8][4];
#pragma unroll
    for (int i = 0; i < 2; i++)
#pragma unroll
        for (int j = 0; j < 8; j++)
#pragma unroll
            for (int l = 0; l < 4; l++) acc[i][j][l] = 0.f;

    const int NC = GK / 32;

    // prefetch helper (inlined twice)
#define PREFETCH(cc, ss)                                                          \
    {                                                                             \
        const int kc = (cc) * 32;                                                 \
        const uint32_t stg = sb + (uint32_t)(ss) * STGB;                          \
        _Pragma("unroll")                                                         \
        for (int i = 0; i < 2; i++) {                                             \
            int idx = tid + i * 256;            /* 0..511 */                      \
            int row = idx >> 2, seg = idx & 3;                                    \
            uint32_t so = (uint32_t)(row * ROWB + seg * 16);                      \
            size_t ea = (size_t)(bm + row) * GK + kc + seg * 8;                   \
            size_t eb = (size_t)(bn + row) * GK + kc + seg * 8;                   \
            cp16(stg + so,            Ah + ea);                                   \
            cp16(stg + MATB + so,     Al + ea);                                   \
            cp16(stg + 2*MATB + so,   Bh + eb);                                   \
            cp16(stg + 3*MATB + so,   Bl + eb);                                   \
        }                                                                         \
        cp_commit();                                                              \
    }

    PREFETCH(0, 0);
    PREFETCH(1, 1);

    // ldmatrix lane addressing (byte offsets within a matrix)
    const uint32_t a_row = (uint32_t)(wm + (lane & 15));
    const uint32_t a_colb = (uint32_t)((lane >> 4) * 16);          // 8 bf16 = 16 B
    const uint32_t b_row0 = (uint32_t)(wn + (lane & 7) + ((lane >> 4) << 3));
    const uint32_t b_colb = (uint32_t)(((lane >> 3) & 1) * 16);

    for (int c = 0; c < NC; c++) {
        if (c == NC - 1) cp_wait<0>(); else cp_wait<1>();
        __syncthreads();
        const uint32_t stg = sb + (uint32_t)(c & 1) * STGB;

#pragma unroll
        for (int k16 = 0; k16 < 2; k16++) {
            const uint32_t kb = (uint32_t)(k16 * 32);   // 16 bf16 = 32 B
            uint32_t ah[2][4], al[2][4], bh[4][4], bl[4][4];
#pragma unroll
            for (int mt = 0; mt < 2; mt++) {
                uint32_t ao = (a_row + mt * 16) * ROWB + kb + a_colb;
                ldsm_x4(stg + ao, ah[mt]);
                ldsm_x4(stg + MATB + ao, al[mt]);
            }
#pragma unroll
            for (int np = 0; np < 4; np++) {
                uint32_t bo = (b_row0 + np * 16) * ROWB + kb + b_colb;
                ldsm_x4(stg + 2*MATB + bo, bh[np]);
                ldsm_x4(stg + 3*MATB + bo, bl[np]);
            }
#pragma unroll
            for (int mt = 0; mt < 2; mt++)
#pragma unroll
                for (int np = 0; np < 4; np++) {
                    mma_bf16(acc[mt][np*2],   ah[mt], bh[np]);       // Ah*Bh (n low)
                    mma_bf16(acc[mt][np*2+1], ah[mt], bh[np] + 2);   // Ah*Bh (n high)
                    mma_bf16(acc[mt][np*2],   ah[mt], bl[np]);       // Ah*Bl
                    mma_bf16(acc[mt][np*2+1], ah[mt], bl[np] + 2);
                    mma_bf16(acc[mt][np*2],   al[mt], bh[np]);       // Al*Bh
                    mma_bf16(acc[mt][np*2+1], al[mt], bh[np] + 2);
                }
        }
        __syncthreads();
        if (c + 2 < NC) PREFETCH(c + 2, c & 1);
    }
#undef PREFETCH

    // epilogue
#pragma unroll
    for (int mt = 0; mt < 2; mt++) {
        int r0 = bm + wm + mt * 16 + (lane >> 2);
#pragma unroll
        for (int nt = 0; nt < 8; nt++) {
            int col = bn + wn + nt * 8 + (lane & 3) * 2;
            float2 v0 = make_float2(acc[mt][nt][0], acc[mt][nt][1]);
            float2 v1 = make_float2(acc[mt][nt][2], acc[mt][nt][3]);
            *(float2*)(C + (size_t)r0 * N + col)       = v0;
            *(float2*)(C + (size_t)(r0 + 8) * N + col) = v1;
        }
    }
}

// ------------------------- fp32 -> bf16 hi/lo split -------------------------
__global__ void cvt_split(const float* __restrict__ x,
                          __nv_bfloat16* __restrict__ hi,
                          __nv_bfloat16* __restrict__ lo, int n)
{
    int i = (blockIdx.x * blockDim.x + threadIdx.x) * 4;
    if (i >= n) return;
    float4 v = *(const float4*)(x + i);
    __nv_bfloat16 hx = __float2bfloat16(v.x), hy = __float2bfloat16(v.y);
    __nv_bfloat16 hz = __float2bfloat16(v.z), hw = __float2bfloat16(v.w);
    __nv_bfloat162 h0, h1, l0, l1;
    h0.x = hx; h0.y = hy; h1.x = hz; h1.y = hw;
    l0.x = __float2bfloat16(v.x - __bfloat162float(hx));
    l0.y = __float2bfloat16(v.y - __bfloat162float(hy));
    l1.x = __float2bfloat16(v.z - __bfloat162float(hz));
    l1.y = __float2bfloat16(v.w - __bfloat162float(hw));
    *(__nv_bfloat162*)(hi + i)     = h0;
    *(__nv_bfloat162*)(hi + i + 2) = h1;
    *(__nv_bfloat162*)(lo + i)     = l0;
    *(__nv_bfloat162*)(lo + i + 2) = l1;
}

// ------------------------- a/b projections -> decay g and beta --------------
__device__ __forceinline__ float softplus_f(float x) {
    return fmaxf(x, 0.f) + log1pf(expf(-fabsf(x)));
}

__global__ void proj_ab_kernel(const float* __restrict__ h,
                               const float* __restrict__ a_w,
                               const float* __restrict__ b_w,
                               const float* __restrict__ A_log,
                               const float* __restrict__ dt_bias,
                               float* __restrict__ gd, float* __restrict__ bt)
{
    int w = (blockIdx.x * blockDim.x + threadIdx.x) >> 5;
    int lane = threadIdx.x & 31;
    if (w >= Mrows) return;
    const float* hr = h + (size_t)w * Dq;
    float acc[16];
#pragma unroll
    for (int p = 0; p < 16; p++) acc[p] = 0.f;
    for (int j = lane * 4; j < Dq; j += 128) {
        float4 hv = *(const float4*)(hr + j);
#pragma unroll
        for (int p = 0; p < 8; p++) {
            float4 av = *(const float4*)(a_w + (size_t)p * Dq + j);
            acc[p] += hv.x * av.x + hv.y * av.y + hv.z * av.z + hv.w * av.w;
            float4 bv = *(const float4*)(b_w + (size_t)p * Dq + j);
            acc[8 + p] += hv.x * bv.x + hv.y * bv.y + hv.z * bv.z + hv.w * bv.w;
        }
    }
#pragma unroll
    for (int p = 0; p < 16; p++)
#pragma unroll
        for (int m = 16; m; m >>= 1)
            acc[p] += __shfl_xor_sync(0xffffffffu, acc[p], m);

    if (lane < 8) {
        float x = acc[lane] + dt_bias[lane];
        gd[w * Hq + lane] = -expf(A_log[lane]) * softplus_f(x);
    } else if (lane < 16) {
        int p = lane - 8;
        bt[w * Hq + p] = 1.f / (1.f + expf(-acc[lane]));
    }
}

// ------------------------- depthwise causal conv (K=4) + SiLU ---------------
__global__ void conv_silu_kernel(const float* __restrict__ in,
                                 const float* __restrict__ w,
                                 float* __restrict__ out, int T, int C)
{
    int i = blockIdx.x * blockDim.x + threadIdx.x;
    int c = i % C;
    int t = (i / C) % T;
    float4 wc = *(const float4*)(w + (size_t)c * 4);
    float acc = 0.f;
    const float* base = in + i;
    if (t >= 3) acc += base[-3 * C] * wc.x;
    if (t >= 2) acc += base[-2 * C] * wc.y;
    if (t >= 1) acc += base[-1 * C] * wc.z;
    acc += base[0] * wc.w;
    out[i] = acc / (1.f + expf(-acc));
}

// ------------------------- l2norm over head dim (128), in place -------------
__global__ void l2norm_kernel(float* __restrict__ x)
{
    int w = (blockIdx.x * blockDim.x + threadIdx.x) >> 5;
    int lane = threadIdx.x & 31;
    float* row = x + (size_t)w * DKq;
    float4 a = *(float4*)(row + lane * 4);
    float ss = a.x * a.x + a.y * a.y + a.z * a.z + a.w * a.w;
#pragma unroll
    for (int m = 16; m; m >>= 1) ss += __shfl_xor_sync(0xffffffffu, ss, m);
    float r = rsqrtf(ss + 1e-6f);
    a.x *= r; a.y *= r; a.z *= r; a.w *= r;
    *(float4*)(row + lane * 4) = a;
}

// ------------------------- gated delta-rule scan ----------------------------
#define TS 16
__global__ void __launch_bounds__(128) scan_kernel(const float* __restrict__ q,
                                                   const float* __restrict__ k,
                                                   const float* __restrict__ v,
                                                   const float* __restrict__ gdec,
                                                   const float* __restrict__ beta,
                                                   float* __restrict__ o)
{
    const int vchunk = blockIdx.x;
    const int h = blockIdx.y;
    const int b = blockIdx.z;
    const int tid = threadIdx.x;
    const int warp = tid >> 5, lane = tid & 31;
    const int col = (warp << 3) + (lane >> 2);
    const int rgrp = lane & 3;
    const int c0 = vchunk * 32;

    __shared__ float ks[TS * 144];
    __shared__ float qs[TS * 144];
    __shared__ float vs[TS * 32];
    __shared__ float gs[TS];
    __shared__ float bs[TS];

    float S[32];
#pragma unroll
    for (int i = 0; i < 32; i++) S[i] = 0.f;
    const float scale = 0.08838834764831843f;

    for (int t0 = 0; t0 < Tq; t0 += TS) {
        __syncthreads();
#pragma unroll
        for (int j = 0; j < 4; j++) {
            int idx = tid + j * 128;
            int s = idx >> 5, f = idx & 31;
            size_t gofs = ((size_t)(b * Tq + t0 + s)) * KDq + h * DKq + f * 4;
            float4 kk = *(const float4*)(k + gofs);
            float4 qq = *(const float4*)(q + gofs);
            int sofs = s * 144 + (f >> 3) * 36 + (f & 7) * 4;
            *(float4*)(ks + sofs) = kk;
            *(float4*)(qs + sofs) = qq;
        }
        {
            int s = tid >> 3, f = tid & 7;
            size_t gofs = ((size_t)(b * Tq + t0 + s)) * VDq + h * DVq + c0 + f * 4;
            *(float4*)(vs + s * 32 + f * 4) = *(const float4*)(v + gofs);
        }
        if (tid < TS) gs[tid] = gdec[(size_t)(b * Tq + t0 + tid) * Hq + h];
        else if (tid < 2 * TS) bs[tid - TS] = beta[(size_t)(b * Tq + t0 + tid - TS) * Hq + h];
        __syncthreads();

#pragma unroll 1
        for (int s = 0; s < TS; s++) {
            float eg = expf(gs[s]);
            const float* ksr = ks + s * 144 + rgrp * 36;
            const float* qsr = qs + s * 144 + rgrp * 36;
            float4 kf[8];
            float kv0 = 0.f, kv1 = 0.f, kv2 = 0.f, kv3 = 0.f;
#pragma unroll
            for (int i = 0; i < 8; i++) {
                kf[i] = *(const float4*)(ksr + i * 4);
                kv0 += kf[i].x * S[4 * i + 0];
                kv1 += kf[i].y * S[4 * i + 1];
                kv2 += kf[i].z * S[4 * i + 2];
                kv3 += kf[i].w * S[4 * i + 3];
            }
            float kv = (kv0 + kv1) + (kv2 + kv3);
            kv += __shfl_xor_sync(0xffffffffu, kv, 1);
            kv += __shfl_xor_sync(0xffffffffu, kv, 2);
            float u = (vs[s * 32 + col] - kv * eg) * bs[s];
            float o0 = 0.f, o1 = 0.f, o2 = 0.f, o3 = 0.f;
#pragma unroll
            for (int i = 0; i < 8; i++) {
                float4 qf = *(const float4*)(qsr + i * 4);
                S[4 * i + 0] = S[4 * i + 0] * eg + kf[i].x * u;
                S[4 * i + 1] = S[4 * i + 1] * eg + kf[i].y * u;
                S[4 * i + 2] = S[4 * i + 2] * eg + kf[i].z * u;
                S[4 * i + 3] = S[4 * i + 3] * eg + kf[i].w * u;
                o0 += qf.x * S[4 * i + 0];
                o1 += qf.y * S[4 * i + 1];
                o2 += qf.z * S[4 * i + 2];
                o3 += qf.w * S[4 * i + 3];
            }
            float ot = (o0 + o1) + (o2 + o3);
            ot += __shfl_xor_sync(0xffffffffu, ot, 1);
            ot += __shfl_xor_sync(0xffffffffu, ot, 2);
            if (rgrp == 0)
                o[(size_t)(b * Tq + t0 + s) * VDq + h * DVq + c0 + col] = ot * scale;
        }
    }
}

// ------------------------- gated RMSNorm -> bf16 hi/lo ----------------------
__global__ void rmsnorm_gate_kernel(const float* __restrict__ o,
                                    const float* __restrict__ gate,
                                    const float* __restrict__ nw,
                                    __nv_bfloat16* __restrict__ oh,
                                    __nv_bfloat16* __restrict__ ol)
{
    int w = (blockIdx.x * blockDim.x + threadIdx.x) >> 5;
    int lane = threadIdx.x & 31;
    const float* orow = o + (size_t)w * DVq;
    float4 o0 = *(const float4*)(orow + lane * 4);
    float4 o1 = *(const float4*)(orow + 128 + lane * 4);
    float ss = o0.x * o0.x + o0.y * o0.y + o0.z * o0.z + o0.w * o0.w
             + o1.x * o1.x + o1.y * o1.y + o1.z * o1.z + o1.w * o1.w;
#pragma unroll
    for (int m = 16; m; m >>= 1) ss += __shfl_xor_sync(0xffffffffu, ss, m);
    float r = rsqrtf(ss * (1.f / 256.f) + 1e-5f);
    const float* grow = gate + (size_t)w * DVq;
    float4 g0 = *(const float4*)(grow + lane * 4);
    float4 g1 = *(const float4*)(grow + 128 + lane * 4);
    float4 w0 = *(const float4*)(nw + lane * 4);
    float4 w1 = *(const float4*)(nw + 128 + lane * 4);
    float f[8];
    f[0] = o0.x * r * w0.x * (g0.x / (1.f + expf(-g0.x)));
    f[1] = o0.y * r * w0.y * (g0.y / (1.f + expf(-g0.y)));
    f[2] = o0.z * r * w0.z * (g0.z / (1.f + expf(-g0.z)));
    f[3] = o0.w * r * w0.w * (g0.w / (1.f + expf(-g0.w)));
    f[4] = o1.x * r * w1.x * (g1.x / (1.f + expf(-g1.x)));
    f[5] = o1.y * r * w1.y * (g1.y / (1.f + expf(-g1.y)));
    f[6] = o1.z * r * w1.z * (g1.z / (1.f + expf(-g1.z)));
    f[7] = o1.w * r * w1.w * (g1.w / (1.f + expf(-g1.w)));
#pragma unroll
    for (int half = 0; half < 2; half++) {
        size_t base = (size_t)w * DVq + half * 128 + lane * 4;
        __nv_bfloat162 hh0, hh1, ll0, ll1;
        float a = f[half*4+0], b2 = f[half*4+1], c = f[half*4+2], d = f[half*4+3];
        hh0.x = __float2bfloat16(a);  hh0.y = __float2bfloat16(b2);
        hh1.x = __float2bfloat16(c);  hh1.y = __float2bfloat16(d);
        ll0.x = __float2bfloat16(a - __bfloat162float(hh0.x));
        ll0.y = __float2bfloat16(b2 - __bfloat162float(hh0.y));
        ll1.x = __float2bfloat16(c - __bfloat162float(hh1.x));
        ll1.y = __float2bfloat16(d - __bfloat162float(hh1.y));
        *(__nv_bfloat162*)(oh + base)     = hh0;
        *(__nv_bfloat162*)(oh + base + 2) = hh1;
        *(__nv_bfloat162*)(ol + base)     = ll0;
        *(__nv_bfloat162*)(ol + base + 2) = ll1;
    }
}

// ------------------------- launch -------------------------------------------
extern "C" void kernel_launch(void* const* d_in, const int* in_sizes, int n_in,
                              void* d_out, int out_size)
{
    const float* h        = (const float*)d_in[0];
    const float* q_w      = (const float*)d_in[1];
    const float* k_w      = (const float*)d_in[2];
    const float* v_w      = (const float*)d_in[3];
    const float* a_w      = (const float*)d_in[4];
    const float* b_w      = (const float*)d_in[5];
    const float* g_w      = (const float*)d_in[6];
    const float* o_w      = (const float*)d_in[7];
    const float* q_conv_w = (const float*)d_in[8];
    const float* k_conv_w = (const float*)d_in[9];
    const float* v_conv_w = (const float*)d_in[10];
    const float* A_log    = (const float*)d_in[11];
    const float* dt_bias  = (const float*)d_in[12];
    const float* o_norm_w = (const float*)d_in[13];
    float* out = (float*)d_out;

    float *qp, *kp, *vp, *qc, *kc, *vc, *gate, *gd, *bt, *orow;
    cudaGetSymbolAddress((void**)&qp, g_qp);
    cudaGetSymbolAddress((void**)&kp, g_kp);
    cudaGetSymbolAddress((void**)&vp, g_vp);
    cudaGetSymbolAddress((void**)&qc, g_qc);
    cudaGetSymbolAddress((void**)&kc, g_kc);
    cudaGetSymbolAddress((void**)&vc, g_vc);
    cudaGetSymbolAddress((void**)&gate, g_gate);
    cudaGetSymbolAddress((void**)&gd, g_gd);
    cudaGetSymbolAddress((void**)&bt, g_bt);
    cudaGetSymbolAddress((void**)&orow, g_orow);

    __nv_bfloat16 *hh, *hl, *qwh, *qwl, *kwh, *kwl, *vwh, *vwl, *gwh, *gwl, *owh, *owl, *onh, *onl;
    cudaGetSymbolAddress((void**)&hh, g_hh);   cudaGetSymbolAddress((void**)&hl, g_hl);
    cudaGetSymbolAddress((void**)&qwh, g_qwh); cudaGetSymbolAddress((void**)&qwl, g_qwl);
    cudaGetSymbolAddress((void**)&kwh, g_kwh); cudaGetSymbolAddress((void**)&kwl, g_kwl);
    cudaGetSymbolAddress((void**)&vwh, g_vwh); cudaGetSymbolAddress((void**)&vwl, g_vwl);
    cudaGetSymbolAddress((void**)&gwh, g_gwh); cudaGetSymbolAddress((void**)&gwl, g_gwl);
    cudaGetSymbolAddress((void**)&owh, g_owh); cudaGetSymbolAddress((void**)&owl, g_owl);
    cudaGetSymbolAddress((void**)&onh, g_onh); cudaGetSymbolAddress((void**)&onl, g_onl);

    cudaFuncSetAttribute(bgemm_nt_split, cudaFuncAttributeMaxDynamicSharedMemorySize, SMEM_GEMM);

    // 0) bf16 hi/lo splits of activations + weights
    cvt_split<<<(Mrows*Dq/4 + 255)/256, 256>>>(h,   hh,  hl,  Mrows*Dq);
    cvt_split<<<(KDq*Dq/4 + 255)/256, 256>>>(q_w, qwh, qwl, KDq*Dq);
    cvt_split<<<(KDq*Dq/4 + 255)/256, 256>>>(k_w, kwh, kwl, KDq*Dq);
    cvt_split<<<(VDq*Dq/4 + 255)/256, 256>>>(v_w, vwh, vwl, VDq*Dq);
    cvt_split<<<(VDq*Dq/4 + 255)/256, 256>>>(g_w, gwh, gwl, VDq*Dq);
    cvt_split<<<(Dq*VDq/4 + 255)/256, 256>>>(o_w, owh, owl, Dq*VDq);

    // 1) projections on tensor cores (split bf16, fp32 accumulate)
    bgemm_nt_split<<<dim3(KDq/128, Mrows/128), 256, SMEM_GEMM>>>(hh, hl, qwh, qwl, qp, KDq);
    bgemm_nt_split<<<dim3(KDq/128, Mrows/128), 256, SMEM_GEMM>>>(hh, hl, kwh, kwl, kp, KDq);
    bgemm_nt_split<<<dim3(VDq/128, Mrows/128), 256, SMEM_GEMM>>>(hh, hl, vwh, vwl, vp, VDq);
    bgemm_nt_split<<<dim3(VDq/128, Mrows/128), 256, SMEM_GEMM>>>(hh, hl, gwh, gwl, gate, VDq);

    // 2) a/b projections -> decay + beta
    proj_ab_kernel<<<(Mrows * 32) / 256, 256>>>(h, a_w, b_w, A_log, dt_bias, gd, bt);

    // 3) causal depthwise conv + SiLU
    conv_silu_kernel<<<(Bq * Tq * KDq) / 256, 256>>>(qp, q_conv_w, qc, Tq, KDq);
    conv_silu_kernel<<<(Bq * Tq * KDq) / 256, 256>>>(kp, k_conv_w, kc, Tq, KDq);
    conv_silu_kernel<<<(Bq * Tq * VDq) / 256, 256>>>(vp, v_conv_w, vc, Tq, VDq);

    // 4) l2 normalize q,k per head
    l2norm_kernel<<<(Bq * Tq * Hq * 32) / 256, 256>>>(qc);
    l2norm_kernel<<<(Bq * Tq * Hq * 32) / 256, 256>>>(kc);

    // 5) gated delta-rule recurrence
    scan_kernel<<<dim3(DVq / 32, Hq, Bq), 128>>>(qc, kc, vc, gd, bt, orow);

    // 6) gated RMSNorm (fused bf16 hi/lo split of the result)
    rmsnorm_gate_kernel<<<(Bq * Tq * Hq * 32) / 256, 256>>>(orow, gate, o_norm_w, onh, onl);

    // 7) output projection -> d_out
    bgemm_nt_split<<<dim3(Dq/128, Mrows/128), 256, SMEM_GEMM>>>(onh, onl, owh, owl, out, Dq);
}